// round 10
// baseline (speedup 1.0000x reference)
#include <cuda_runtime.h>

#define NN 8192
#define BINS 8192            // bin = fkey >> 19  (13 bits: sign+exp+4 mantissa)

// ---- inversion kernel geometry ----
#define JT 256
#define INV_G (NN / JT)              // 32
#define INV_BLOCKS (INV_G * INV_G)   // 1024 (528 active)

// Scratch (allocation-free device globals; everything consumed is re-initialized each call)
__device__ unsigned int       g_hist[2][BINS];     // per-bin counts (zeroed in K0)
__device__ unsigned int       g_base[2][BINS];     // exclusive prefix (written in K2)
__device__ unsigned int       g_cursor[2][BINS];   // scatter cursors (written in K2, consumed in K3)
__device__ unsigned long long g_binkeys[2][NN];    // keys grouped by bin
__device__ int                g_r[NN];             // rank of X[p]
__device__ int                g_B[NN];             // argsort(X_hat)
__device__ int                g_tau[NN];           // tau = B o r
__device__ unsigned int       g_count;
__device__ unsigned int       g_done;

// Monotone uint32 mapping of float (total order == float < for finite values)
__device__ __forceinline__ unsigned int fkey(float f) {
    unsigned int u = __float_as_uint(f);
    return (u & 0x80000000u) ? ~u : (u | 0x80000000u);
}
// 45-bit key: value order, index tie-break (exact stable-argsort semantics). idx < 8192 fits 13 bits.
__device__ __forceinline__ unsigned long long make_key(float f, int idx) {
    return (((unsigned long long)fkey(f)) << 13) | (unsigned int)idx;
}
// bin(key) = key >> 32 = fkey >> 19  (just the high word)

// K0: zero histograms + counters. grid 64x256 covers 2*BINS.
__global__ void zero_kernel() {
    const int i = blockIdx.x * 256 + threadIdx.x;
    ((unsigned int*)g_hist)[i] = 0;
    if (i == 0) { g_count = 0; g_done = 0; }
}

// K1: histogram of bins for both arrays. grid 64x256 covers 2*NN.
__global__ void hist_kernel(const float* __restrict__ X, const float* __restrict__ Xh) {
    const int i = blockIdx.x * 256 + threadIdx.x;
    const int arr = i >> 13;
    const int p = i & (NN - 1);
    const float f = arr ? Xh[p] : X[p];
    atomicAdd(&g_hist[arr][fkey(f) >> 19], 1u);
}

// K2: exclusive scan of each array's 8192-bin histogram. One block, 1024 threads, 8 bins/thread.
__global__ void scan_kernel() {
    __shared__ unsigned int ssum[1024];
    const int t = threadIdx.x;
    for (int arr = 0; arr < 2; arr++) {
        unsigned int h[8];
        unsigned int s = 0;
        #pragma unroll
        for (int k = 0; k < 8; k++) { h[k] = g_hist[arr][t * 8 + k]; s += h[k]; }
        ssum[t] = s;
        __syncthreads();
        unsigned int v = s;  // inclusive scan value for this thread's chunk
        for (int off = 1; off < 1024; off <<= 1) {
            const unsigned int u = (t >= off) ? ssum[t - off] : 0u;
            __syncthreads();
            v += u;
            ssum[t] = v;
            __syncthreads();
        }
        unsigned int run = v - s;  // exclusive prefix of this chunk
        #pragma unroll
        for (int k = 0; k < 8; k++) {
            g_base[arr][t * 8 + k] = run;
            g_cursor[arr][t * 8 + k] = run;
            run += h[k];
        }
        __syncthreads();
    }
}

// K3: scatter keys into their bins (order within bin arbitrary — ranks are order-independent).
__global__ void scatterkeys_kernel(const float* __restrict__ X, const float* __restrict__ Xh) {
    const int i = blockIdx.x * 256 + threadIdx.x;
    const int arr = i >> 13;
    const int p = i & (NN - 1);
    const float f = arr ? Xh[p] : X[p];
    const unsigned long long k = make_key(f, p);
    const unsigned int b = (unsigned int)(k >> 32);
    const unsigned int slot = atomicAdd(&g_cursor[arr][b], 1u);
    g_binkeys[arr][slot] = k;
}

// K4: exact rank = base[bin] + #{same-bin keys < key}. Writes r (arr 0) / scatters B (arr 1).
__global__ void rankscatter_kernel() {
    const int i = blockIdx.x * 256 + threadIdx.x;
    const int arr = i >> 13;
    const int g = i & (NN - 1);
    const unsigned long long k = g_binkeys[arr][g];
    const unsigned int b = (unsigned int)(k >> 32);
    const unsigned int base = g_base[arr][b];
    const unsigned int m = g_hist[arr][b];
    const unsigned long long* __restrict__ bk = &g_binkeys[arr][base];
    unsigned int cnt = 0;
    for (unsigned int j = 0; j < m; j++)
        cnt += (__ldg(&bk[j]) < k) ? 1u : 0u;
    const unsigned int r = base + cnt;
    const int p = (int)(k & (unsigned long long)(NN - 1));
    if (arr) g_B[r] = p;
    else     g_r[p] = (int)r;
}

// K5: tau[i] = B[r[i]]
__global__ void tau_kernel() {
    const int i = blockIdx.x * 256 + threadIdx.x;
    g_tau[i] = g_B[g_r[i]];
}

// K6: inversions of tau over 256x256 upper-triangular tiles; last block finalizes output.
__global__ void inv_kernel(float* __restrict__ out) {
    __shared__ __align__(16) int sh[JT];
    const int I = blockIdx.y, J = blockIdx.x;
    const int tid = threadIdx.x;

    if (J >= I) {
        sh[tid] = g_tau[J * JT + tid];
        const int v = g_tau[I * JT + tid];
        __syncthreads();
        unsigned int cnt = 0;
        if (J > I) {
            const int4* __restrict__ sh4 = (const int4*)sh;
            #pragma unroll 16
            for (int j = 0; j < JT / 4; j++) {
                const int4 s = sh4[j];
                cnt += (v > s.x) + (v > s.y) + (v > s.z) + (v > s.w);
            }
        } else {
            for (int j = tid + 1; j < JT; j++)
                cnt += (v > sh[j]) ? 1u : 0u;
        }
        cnt = __reduce_add_sync(0xffffffffu, cnt);
        if ((tid & 31) == 0) atomicAdd(&g_count, cnt);
        __syncthreads();
    }

    // Completion detection: every block signals; the last one writes the result.
    if (tid == 0) {
        __threadfence();
        const unsigned int d = atomicAdd(&g_done, 1u);
        if (d == INV_BLOCKS - 1) {
            const unsigned int tot = atomicAdd(&g_count, 0u);
            out[0] = (float)(2.0 * (double)tot / ((double)NN * (double)(NN - 1)));
        }
    }
}

extern "C" void kernel_launch(void* const* d_in, const int* in_sizes, int n_in,
                              void* d_out, int out_size) {
    const float* X  = (const float*)d_in[0];
    const float* Xh = (const float*)d_in[1];
    float* out = (float*)d_out;

    zero_kernel<<<(2 * BINS) / 256, 256>>>();
    hist_kernel<<<(2 * NN) / 256, 256>>>(X, Xh);
    scan_kernel<<<1, 1024>>>();
    scatterkeys_kernel<<<(2 * NN) / 256, 256>>>(X, Xh);
    rankscatter_kernel<<<(2 * NN) / 256, 256>>>();
    tau_kernel<<<NN / 256, 256>>>();
    dim3 gi(INV_G, INV_G);
    inv_kernel<<<gi, JT>>>(out);
}

// round 12
// speedup vs baseline: 3.2235x; 3.2235x over previous
#include <cuda_runtime.h>

#define NN 8192

// ---- K1 (rank) ----
#define NBINS 8192            // bin = fkey >> 19 (sign + exp + 4 mantissa bits)
#define K1_T 1024
#define K1_SLICES 16          // blocks per array; each ranks NN/K1_SLICES elements
#define K1_EPB (NN / K1_SLICES)   // 512

// ---- K2 (inversions) ----
#define K2_T 1024
#define TILE 256
#define NTILES (NN / TILE)    // 32
#define NWORDS (NN / 32)      // 256 bitmap words per tile
#define K2_BLOCKS NTILES      // 32 (block I handles i-tile I)

__device__ int g_r[NN];            // rank of X[p]
__device__ int g_B[NN];            // argsort(X_hat): B[rank] = index
__device__ unsigned int g_count;
__device__ unsigned int g_done;

// Monotone uint32 mapping of float (total order == float < for finite values)
__device__ __forceinline__ unsigned int fkey(float f) {
    unsigned int u = __float_as_uint(f);
    return (u & 0x80000000u) ? ~u : (u | 0x80000000u);
}
// Full 45-bit key = (fkey << 13) | idx. bin = key >> 32 = fkey >> 19.
// Within one bin the high bits are identical, so ordering == ordering of the
// LOW 32 bits  lo = (fkey << 13) | idx  (exact stable-argsort tie-break).

// K1: exact ranks via redundant per-block smem histogram + scan + bin-grouped compare.
// grid (K1_SLICES, 2 arrays), block K1_T. Dyn smem: hist | cursor | binlo | warpsum.
__global__ void rank_kernel(const float* __restrict__ X, const float* __restrict__ Xh) {
    extern __shared__ unsigned int s1[];
    unsigned int* hist    = s1;                 // [NBINS] counts (kept intact)
    unsigned int* cursor  = s1 + NBINS;         // [NBINS] excl. prefix -> end after scatter
    unsigned int* binlo   = s1 + 2 * NBINS;     // [NN] low-32 keys grouped by bin
    unsigned int* warpsum = s1 + 3 * NBINS;     // [32]

    const int arr = blockIdx.y;
    const float* __restrict__ src = arr ? Xh : X;
    const int t = threadIdx.x;

    // zero histogram
    #pragma unroll
    for (int k = 0; k < NBINS / K1_T; k++) hist[t + k * K1_T] = 0;
    __syncthreads();

    // load ALL elements (8/thread), histogram; keep keys in registers
    unsigned int lo[8], bin[8];
    #pragma unroll
    for (int k = 0; k < 8; k++) {
        const int e = t + k * K1_T;
        const unsigned int fk = fkey(src[e]);
        lo[k]  = (fk << 13) | (unsigned int)e;
        bin[k] = fk >> 19;
        atomicAdd(&hist[bin[k]], 1u);
    }
    __syncthreads();

    // exclusive scan of hist -> cursor (thread t owns bins [8t, 8t+8))
    unsigned int h[8], tsum = 0;
    #pragma unroll
    for (int k = 0; k < 8; k++) { h[k] = hist[t * 8 + k]; tsum += h[k]; }
    unsigned int incl = tsum;
    #pragma unroll
    for (int off = 1; off < 32; off <<= 1) {
        const unsigned int u = __shfl_up_sync(0xffffffffu, incl, off);
        if ((t & 31) >= off) incl += u;
    }
    if ((t & 31) == 31) warpsum[t >> 5] = incl;
    __syncthreads();
    if (t < 32) {
        const unsigned int w = warpsum[t];
        unsigned int wi = w;
        #pragma unroll
        for (int off = 1; off < 32; off <<= 1) {
            const unsigned int u = __shfl_up_sync(0xffffffffu, wi, off);
            if (t >= off) wi += u;
        }
        warpsum[t] = wi - w;   // exclusive warp base
    }
    __syncthreads();
    unsigned int run = warpsum[t >> 5] + (incl - tsum);
    #pragma unroll
    for (int k = 0; k < 8; k++) { cursor[t * 8 + k] = run; run += h[k]; }
    __syncthreads();

    // scatter low-keys into bin-grouped order (in-bin order irrelevant)
    #pragma unroll
    for (int k = 0; k < 8; k++) {
        const unsigned int slot = atomicAdd(&cursor[bin[k]], 1u);
        binlo[slot] = lo[k];
    }
    __syncthreads();

    // exact rank for this block's slice only
    if (t < K1_EPB) {
        const int e = blockIdx.x * K1_EPB + t;
        const unsigned int fk = fkey(src[e]);      // L1-hot reload
        const unsigned int mylo = (fk << 13) | (unsigned int)e;
        const unsigned int b = fk >> 19;
        const unsigned int end = cursor[b];        // base + count
        const unsigned int start = end - hist[b];
        unsigned int cnt = 0;
        for (unsigned int j = start; j < end; j++)
            cnt += (binlo[j] < mylo) ? 1u : 0u;
        const unsigned int r = start + cnt;
        if (arr) g_B[r] = e;
        else     g_r[e] = (int)r;
    }
    if (arr == 0 && blockIdx.x == 0 && t == 0) { g_count = 0; g_done = 0; }
}

// K2: tau = B o r, inversion count via per-tile value bitmaps + prefix popcounts,
// finalize in last-done block. grid K2_BLOCKS, block K2_T.
__global__ void inv_kernel(float* __restrict__ out) {
    extern __shared__ unsigned int s2[];
    unsigned int*   bitmap = s2;                                   // [NTILES*NWORDS] 32KB
    unsigned short* pref   = (unsigned short*)(s2 + NTILES * NWORDS); // [NTILES*NWORDS] 16KB
    unsigned short* tau    = pref + NTILES * NWORDS;               // [NN] 16KB
    __shared__ unsigned int blocksum;

    const int t = threadIdx.x;

    #pragma unroll
    for (int k = 0; k < (NTILES * NWORDS) / K2_T; k++) bitmap[t + k * K2_T] = 0;
    if (t == 0) blocksum = 0;
    __syncthreads();

    // gather tau (redundantly per block) and set value bits per position-tile
    #pragma unroll
    for (int k = 0; k < NN / K2_T; k++) {
        const int i = t + k * K2_T;
        const int v = g_B[g_r[i]];
        tau[i] = (unsigned short)v;
        atomicOr(&bitmap[(i >> 8) * NWORDS + (v >> 5)], 1u << (v & 31));
    }
    __syncthreads();

    // per-tile word-exclusive prefix popcounts (warp w handles tile w)
    {
        const int w = t >> 5, l = t & 31;
        unsigned int c[8], csum = 0;
        #pragma unroll
        for (int k = 0; k < 8; k++) {
            c[k] = __popc(bitmap[w * NWORDS + l * 8 + k]);
            csum += c[k];
        }
        unsigned int inc = csum;
        #pragma unroll
        for (int off = 1; off < 32; off <<= 1) {
            const unsigned int u = __shfl_up_sync(0xffffffffu, inc, off);
            if (l >= off) inc += u;
        }
        unsigned int run = inc - csum;
        #pragma unroll
        for (int k = 0; k < 8; k++) {
            pref[w * NWORDS + l * 8 + k] = (unsigned short)run;
            run += c[k];
        }
    }
    __syncthreads();

    // count inversions for i in tile I = blockIdx.x; 4 threads per row
    const int I = blockIdx.x;
    const int il = t & (TILE - 1);
    const int part = t >> 8;                   // 0..3
    const unsigned int v = tau[I * TILE + il];
    unsigned int cnt = 0;

    if (part == 0) {
        // cross-tile: all positions in tiles J > I are after i; count values < v
        const unsigned int w = v >> 5;
        const unsigned int mask = (1u << (v & 31)) - 1u;
        for (int J = I + 1; J < NTILES; J++)
            cnt += (unsigned int)pref[J * NWORDS + w] + __popc(bitmap[J * NWORDS + w] & mask);
    }
    {
        // within-tile: j in (il, 256), split across 4 parts
        const unsigned short* tt = tau + I * TILE;
        int lo = il + 1;
        const int plo = part * 64;
        if (plo > lo) lo = plo;
        const int hi = plo + 64;
        for (int j = lo; j < hi; j++)
            cnt += (tt[j] < v) ? 1u : 0u;
    }
    cnt = __reduce_add_sync(0xffffffffu, cnt);
    if ((t & 31) == 0) atomicAdd(&blocksum, cnt);
    __syncthreads();

    if (t == 0) {
        atomicAdd(&g_count, blocksum);
        __threadfence();
        const unsigned int d = atomicAdd(&g_done, 1u);
        if (d == K2_BLOCKS - 1) {
            const unsigned int tot = atomicAdd(&g_count, 0u);
            out[0] = (float)(2.0 * (double)tot / ((double)NN * (double)(NN - 1)));
        }
    }
}

extern "C" void kernel_launch(void* const* d_in, const int* in_sizes, int n_in,
                              void* d_out, int out_size) {
    const float* X  = (const float*)d_in[0];
    const float* Xh = (const float*)d_in[1];
    float* out = (float*)d_out;

    const int smem1 = (3 * NBINS + 32) * (int)sizeof(unsigned int);          // 98,432 B
    const int smem2 = NTILES * NWORDS * 4 + NTILES * NWORDS * 2 + NN * 2;    // 65,536 B
    // Idempotent opt-in for >48KB dynamic smem (host API, not stream-ordered).
    cudaFuncSetAttribute(rank_kernel, cudaFuncAttributeMaxDynamicSharedMemorySize, smem1);
    cudaFuncSetAttribute(inv_kernel,  cudaFuncAttributeMaxDynamicSharedMemorySize, smem2);

    dim3 g1(K1_SLICES, 2);
    rank_kernel<<<g1, K1_T, smem1>>>(X, Xh);
    inv_kernel<<<K2_BLOCKS, K2_T, smem2>>>(out);
}